// round 7
// baseline (speedup 1.0000x reference)
#include <cuda_runtime.h>
#include <cuda_bf16.h>
#include <math.h>
#include <float.h>

#define NB 144          // total blocks (1 CTA/SM, 144 <= 148)
#define GROUPS 4        // independent groups
#define GNB 36          // blocks per group
#define SPG 8           // timesteps per group
#define NT 1024         // threads per block
#define N_ 4096
#define S_ 32
#define D_ 128
#define MAXP 4352       // worst-case padded dim bound (multiple of 256)
#define ITS 20
#define EPSK 1e-6f

// ---------------- persistent scratch (__device__ globals: allocation-free) ----------------
__device__ __align__(16) float  g_Xg[(size_t)S_ * N_ * D_];
__device__ float  g_nrm[S_ * N_];
__device__ __align__(16) float          g_M [(size_t)GROUPS * MAXP * MAXP];
__device__ __align__(16) __nv_bfloat16  g_K [(size_t)GROUPS * MAXP * MAXP];
__device__ __align__(16) __nv_bfloat16  g_KT[(size_t)GROUPS * MAXP * MAXP];
__device__ __align__(16) float  g_u [GROUPS][MAXP];
__device__ __align__(16) float  g_bv[GROUPS][MAXP];
__device__ int    g_perm[GROUPS][N_];
__device__ int    g_ntA [GROUPS];
__device__ float  g_pA  [GROUPS];
__device__ float  g_pmax[GROUPS][GNB];
__device__ double g_psum[GROUPS][GNB];
__device__ double g_pres[GROUPS][GNB];
__device__ double g_res [S_];
__device__ unsigned long long g_barCnt[GROUPS * 16];
__device__ unsigned long long g_doneCnt;

// ---------------- group barrier: monotonic 64-bit counter ----------------
__device__ __forceinline__ void gbar_sync(unsigned long long* cnt, unsigned long long tgt) {
    __syncthreads();
    if (threadIdx.x == 0) {
        __threadfence();
        atomicAdd(cnt, 1ULL);
        while (*(volatile unsigned long long*)cnt < tgt) { __nanosleep(32); }
        __threadfence();
    }
    __syncthreads();
}
#define GBAR() do { ++barK; gbar_sync(cntp, barBase + (unsigned long long)barK * GNB); } while (0)

// ---------------- FFMA-only expf ----------------
__device__ __forceinline__ float fast_exp(float x) {
    const float L2E = 1.4426950408889634f;
    float y = fmaf(x, L2E, 12582912.0f);
    int   n = __float_as_int(y) - 0x4B400000;
    float r = y - 12582912.0f;
    float f = fmaf(x, L2E, -r);
    float p =        1.540353040e-4f;
    p = fmaf(p, f,   1.333355815e-3f);
    p = fmaf(p, f,   9.618129107e-3f);
    p = fmaf(p, f,   5.550410866e-2f);
    p = fmaf(p, f,   2.402265070e-1f);
    p = fmaf(p, f,   6.931471806e-1f);
    p = fmaf(p, f,   1.0f);
    return p * __int_as_float((n + 127) << 23);
}

__device__ __forceinline__ float warpMaxF(float v) {
    #pragma unroll
    for (int o = 16; o; o >>= 1) v = fmaxf(v, __shfl_down_sync(0xffffffffu, v, o));
    return v;
}
__device__ __forceinline__ float warpSumF(float v) {
    #pragma unroll
    for (int o = 16; o; o >>= 1) v += __shfl_down_sync(0xffffffffu, v, o);
    return v;
}
__device__ __forceinline__ double warpSumD(double v) {
    #pragma unroll
    for (int o = 16; o; o >>= 1) v += __shfl_down_sync(0xffffffffu, v, o);
    return v;
}
__device__ __forceinline__ void warpSum2F(float& v0, float& v1) {
    #pragma unroll
    for (int o = 16; o; o >>= 1) {
        v0 += __shfl_down_sync(0xffffffffu, v0, o);
        v1 += __shfl_down_sync(0xffffffffu, v1, o);
    }
}

// ---------------- packed f32x2 helpers ----------------
__device__ __forceinline__ unsigned long long pk2f(float a, float b) {
    unsigned long long r;
    asm("mov.b64 %0, {%1, %2};" : "=l"(r) : "f"(a), "f"(b));
    return r;
}
__device__ __forceinline__ float2 upk2f(unsigned long long v) {
    float2 r;
    asm("mov.b64 {%0, %1}, %2;" : "=f"(r.x), "=f"(r.y) : "l"(v));
    return r;
}
__device__ __forceinline__ void fmaf2(unsigned long long& d, unsigned long long a, unsigned long long b) {
    asm("fma.rn.f32x2 %0, %1, %2, %0;" : "+l"(d) : "l"(a), "l"(b));
}
// bf16x2 word -> f32x2 pair: 2 ALU ops, no F2F
__device__ __forceinline__ unsigned long long bf2f2(unsigned w) {
    unsigned long long r;
    asm("{\n\t.reg .b32 lo, hi;\n\t"
        "shl.b32 lo, %1, 16;\n\t"
        "and.b32 hi, %1, 0xFFFF0000;\n\t"
        "mov.b64 %0, {lo, hi};\n\t}"
        : "=l"(r) : "r"(w));
    return r;
}

__global__ void __launch_bounds__(NT, 1)
sinkhorn_all(const float* __restrict__ X, const int* __restrict__ T, float* __restrict__ out)
{
    __shared__ __align__(16) float sh[8448];
    __shared__ float  s_f[32];
    __shared__ double s_d[32];
    __shared__ float  s_delta, s_efflam;

    const int tid  = threadIdx.x;
    const int bid  = blockIdx.x;
    const int lane = tid & 31;
    const int wid  = tid >> 5;
    const int grp  = bid / GNB;
    const int lb   = bid - grp * GNB;
    const int gw   = lb * 32 + wid;     // warp within group (0..GNB*32-1)
    const int GW   = GNB * 32;

    unsigned long long* cntp = &g_barCnt[grp * 16];
    unsigned long long v0 = *(volatile unsigned long long*)cntp;
    unsigned long long barBase = v0 - (v0 % (unsigned long long)GNB);
    int barK = 0;

    unsigned long long doneBase = 0;
    if (bid == 0 && tid == 0) {
        unsigned long long dv = *(volatile unsigned long long*)&g_doneCnt;
        doneBase = dv - (dv % (unsigned long long)NB);
    }

    float*         Mg  = g_M  + (size_t)grp * MAXP * MAXP;
    __nv_bfloat16* Kg  = g_K  + (size_t)grp * MAXP * MAXP;
    __nv_bfloat16* KTg = g_KT + (size_t)grp * MAXP * MAXP;
    float*         ug  = g_u [grp];
    float*         bvg = g_bv[grp];
    int*           permg = g_perm[grp];

    // ---------------- A0: stable permutation (per group) ----------------
    if (lb == 0) {
        int* cnt = (int*)sh;
        int base = tid * 4;
        int tv0 = T[base], tv1 = T[base+1], tv2 = T[base+2], tv3 = T[base+3];
        int c = (tv0 > 0) + (tv1 > 0) + (tv2 > 0) + (tv3 > 0);
        cnt[tid] = c;
        __syncthreads();
        for (int off = 1; off < NT; off <<= 1) {
            int vv  = cnt[tid];
            int add = (tid >= off) ? cnt[tid - off] : 0;
            __syncthreads();
            cnt[tid] = vv + add;
            __syncthreads();
        }
        int total = cnt[NT - 1];
        int excl  = cnt[tid] - c;
        int tpos = excl, cpos = total + base - excl;
        if (tv0 > 0) permg[tpos++] = base + 0; else permg[cpos++] = base + 0;
        if (tv1 > 0) permg[tpos++] = base + 1; else permg[cpos++] = base + 1;
        if (tv2 > 0) permg[tpos++] = base + 2; else permg[cpos++] = base + 2;
        if (tv3 > 0) permg[tpos++] = base + 3; else permg[cpos++] = base + 3;
        if (tid == NT - 1) { g_ntA[grp] = total; g_pA[grp] = (float)total / (float)N_; }
    }
    GBAR();

    const int   nt = g_ntA[grp];
    const int   nc = N_ - nt;
    const float p  = g_pA[grp];
    const int   R = nt + 1, C = nc + 1;
    const int   RPP = (R + 255) & ~255;
    const int   CPP = (C + 255) & ~255;
    const float a_in = p / (float)nt, a_last = 1.0f - p;
    const float b_in = (1.0f - p) / (float)nc, b_last = p;

    // ---------------- A1: gather 8 timesteps + squared norms ----------------
    for (int job = gw; job < SPG * N_; job += GW) {
        int s = grp * SPG + (job >> 12);
        int r = job & (N_ - 1);
        int src = permg[r];
        const float4* sp = (const float4*)(X + ((size_t)src * S_ + s) * D_);
        float4 vv = sp[lane];
        ((float4*)(g_Xg + ((size_t)s * N_ + r) * D_))[lane] = vv;
        float sq = vv.x*vv.x + vv.y*vv.y + vv.z*vv.z + vv.w*vv.w;
        sq = warpSumF(sq);
        if (lane == 0) g_nrm[s * N_ + r] = sq;
    }
    GBAR();

    // ================== per-timestep loop ==================
    for (int sl = 0; sl < SPG; sl++) {
        const int s = grp * SPG + sl;
        const float* Xt  = g_Xg + (size_t)s * N_ * D_;
        const float* nrm = g_nrm + s * N_;

        // ---------- B1: M = nx + ny - 2*Xt*Xc^T (128x128 tiles, f32x2) ----------
        {
            float* As = sh;
            float* Bs = sh + 4096;
            const int tilesI = (nt + 127) >> 7;
            const int tilesJ = (nc + 127) >> 7;
            const int nTiles = tilesI * tilesJ;
            const int lrow = tid & 127;
            const int ld4  = tid >> 7;
            const int tx = lane;
            const int ty = wid;
            float  lmax = -FLT_MAX;
            double lsum = 0.0;

            for (int tile = lb; tile < nTiles; tile += GNB) {
                int ti = tile / tilesJ, tj = tile - ti * tilesJ;
                int i0 = ti << 7, j0 = tj << 7;
                int arow = i0 + lrow; if (arow >= nt) arow = nt - 1;
                int brow = j0 + lrow; if (brow >= nc) brow = nc - 1;
                const float* ap = Xt + (size_t)arow * D_ + ld4 * 4;
                const float* bp = Xt + (size_t)(nt + brow) * D_ + ld4 * 4;

                unsigned long long acc2[4][2] = {};

                for (int d0 = 0; d0 < D_; d0 += 32) {
                    __syncthreads();
                    float4 av = *(const float4*)(ap + d0);
                    float4 bw = *(const float4*)(bp + d0);
                    int dd0 = ld4 * 4;
                    As[(dd0+0)*128 + lrow] = av.x;  As[(dd0+1)*128 + lrow] = av.y;
                    As[(dd0+2)*128 + lrow] = av.z;  As[(dd0+3)*128 + lrow] = av.w;
                    Bs[(dd0+0)*128 + lrow] = bw.x;  Bs[(dd0+1)*128 + lrow] = bw.y;
                    Bs[(dd0+2)*128 + lrow] = bw.z;  Bs[(dd0+3)*128 + lrow] = bw.w;
                    __syncthreads();
                    #pragma unroll
                    for (int dd = 0; dd < 32; dd++) {
                        float4 a4 = *(const float4*)&As[dd*128 + ty*4];
                        ulonglong2 b2 = *(const ulonglong2*)&Bs[dd*128 + tx*4];
                        unsigned long long ax = pk2f(a4.x, a4.x);
                        unsigned long long ay = pk2f(a4.y, a4.y);
                        unsigned long long az = pk2f(a4.z, a4.z);
                        unsigned long long aw = pk2f(a4.w, a4.w);
                        fmaf2(acc2[0][0], ax, b2.x); fmaf2(acc2[0][1], ax, b2.y);
                        fmaf2(acc2[1][0], ay, b2.x); fmaf2(acc2[1][1], ay, b2.y);
                        fmaf2(acc2[2][0], az, b2.x); fmaf2(acc2[2][1], az, b2.y);
                        fmaf2(acc2[3][0], aw, b2.x); fmaf2(acc2[3][1], aw, b2.y);
                    }
                }
                float tsum = 0.0f;
                #pragma unroll
                for (int rr = 0; rr < 4; rr++) {
                    int i = i0 + ty * 4 + rr;
                    if (i >= nt) break;
                    float nx = nrm[i];
                    float2 c01 = upk2f(acc2[rr][0]);
                    float2 c23 = upk2f(acc2[rr][1]);
                    float cv[4] = { c01.x, c01.y, c23.x, c23.y };
                    #pragma unroll
                    for (int cc = 0; cc < 4; cc++) {
                        int j = j0 + tx * 4 + cc;
                        if (j >= nc) break;
                        float m = fmaf(-2.0f, cv[cc], nx + nrm[nt + j]);
                        Mg[(size_t)i * CPP + j] = m;
                        lmax = fmaxf(lmax, m);
                        tsum += m;
                    }
                }
                lsum += (double)tsum;
            }
            lmax = warpMaxF(lmax);
            lsum = warpSumD(lsum);
            __syncthreads();
            if (lane == 0) { s_f[wid] = lmax; s_d[wid] = lsum; }
            __syncthreads();
            if (wid == 0) {
                float  m2 = s_f[lane];
                double s2 = s_d[lane];
                m2 = warpMaxF(m2);
                s2 = warpSumD(s2);
                if (lane == 0) { g_pmax[grp][lb] = m2; g_psum[grp][lb] = s2; }
            }
        }
        GBAR();

        // ---------- B2: reduce GNB partials (identical fixed order in every block) ----------
        if (tid == 0) {
            float  dmax = -FLT_MAX;
            double dsum = 0.0;
            #pragma unroll 4
            for (int k2 = 0; k2 < GNB; k2++) {
                dmax = fmaxf(dmax, __ldcg(&g_pmax[grp][k2]));
                dsum += __ldcg(&g_psum[grp][k2]);
            }
            s_delta  = dmax;
            s_efflam = (float)(((double)nt * (double)nc) / dsum);
        }
        __syncthreads();
        const float delta  = s_delta;
        const float efflam = s_efflam;

        // ---------- B3: K = exp(-efflam*Mt)+eps (bf16, segment-permuted), K^T transpose ----------
        {
            const int rowStrips = RPP >> 5, colStrips = CPP >> 7;
            const int nStr = rowStrips * colStrips;
            const int srow = wid;
            const int tj = tid >> 3;
            const int io = (tid & 7) * 4;
            const float kdelta = fast_exp(-efflam * delta) + EPSK;

            for (int str = lb; str < nStr; str += GNB) {
                int sr = str / colStrips, sc = str - sr * colStrips;
                int i0 = sr << 5, j0 = sc << 7;
                int i = i0 + srow;
                float kq[4];
                #pragma unroll
                for (int q = 0; q < 4; q++) {
                    int j = j0 + lane * 4 + q;
                    float kv;
                    if (i < nt && j < nc) {
                        float m = __ldcg(&Mg[(size_t)i * CPP + j]);
                        kv = fast_exp(-efflam * m) + EPSK;
                    } else if (i == nt && j < nc) kv = kdelta;
                    else if (j == nc && i < nt)   kv = kdelta;
                    else if (i == nt && j == nc)  kv = 1.0f + EPSK;
                    else                          kv = 0.0f;
                    kq[q] = kv;
                }
                *(float4*)&sh[srow * 132 + lane * 4] = make_float4(kq[0], kq[1], kq[2], kq[3]);
                {
                    union { __nv_bfloat162 h[2]; uint2 u; } cv;
                    cv.h[0] = __floats2bfloat162_rn(kq[0], kq[1]);
                    cv.h[1] = __floats2bfloat162_rn(kq[2], kq[3]);
                    int halfOff = (j0 & ~255) + lane * 8 + ((j0 & 128) ? 4 : 0);
                    *(uint2*)&Kg[(size_t)i * CPP + halfOff] = cv.u;
                }
                __syncthreads();
                {
                    union { __nv_bfloat162 h[2]; uint2 u; } cv;
                    cv.h[0] = __floats2bfloat162_rn(sh[(io+0)*132 + tj], sh[(io+1)*132 + tj]);
                    cv.h[1] = __floats2bfloat162_rn(sh[(io+2)*132 + tj], sh[(io+3)*132 + tj]);
                    int ii = i0 + io;
                    int halfOff = (ii & ~255) + ((ii & 127) >> 2) * 8 + ((ii & 128) ? 4 : 0);
                    *(uint2*)&KTg[(size_t)(j0 + tj) * RPP + halfOff] = cv.u;
                }
                __syncthreads();
            }
            if (lb == 0) {
                for (int r2 = tid; r2 < RPP; r2 += NT)
                    ug[r2] = (r2 < nt) ? a_in : ((r2 == nt) ? a_last : 0.0f);
                for (int c2 = tid; c2 < CPP; c2 += NT)
                    if (c2 >= C) bvg[c2] = 0.0f;
            }
        }
        GBAR();

        // ---------- Sinkhorn: 20 iterations + final v pass ----------
        const int segU = RPP >> 8;
        const int segB = CPP >> 8;
        const float4* ug4  = (const float4*)ug;
        const float4* bvg4 = (const float4*)bvg;

        for (int it = 0; it <= ITS; it++) {
            // pass1: bv = b / (K^T u)   (u staged in smem, conflict-free)
            for (int i4 = tid; i4 < (RPP >> 2); i4 += NT)
                ((float4*)sh)[i4] = __ldcg(ug4 + i4);
            __syncthreads();
            for (int cb = gw * 2; cb < C; cb += GW * 2) {
                const int c1 = (cb + 1 < C) ? (cb + 1) : cb;
                const uint4* Kr0 = (const uint4*)(KTg + (size_t)cb * RPP);
                const uint4* Kr1 = (const uint4*)(KTg + (size_t)c1 * RPP);
                unsigned long long ac00 = 0, ac01 = 0, ac10 = 0, ac11 = 0;
                uint4 k0 = __ldcg(Kr0 + lane);
                uint4 k1 = __ldcg(Kr1 + lane);
                for (int sg = 0; sg < segU; sg++) {
                    const int nx = (sg + 1 < segU) ? (sg + 1) : sg;   // prefetch
                    uint4 nk0 = __ldcg(Kr0 + nx * 32 + lane);
                    uint4 nk1 = __ldcg(Kr1 + nx * 32 + lane);
                    ulonglong2 U0 = *(const ulonglong2*)(sh + sg * 256 + lane * 4);
                    ulonglong2 U1 = *(const ulonglong2*)(sh + sg * 256 + 128 + lane * 4);
                    fmaf2(ac00, bf2f2(k0.x), U0.x); fmaf2(ac01, bf2f2(k0.y), U0.y);
                    fmaf2(ac00, bf2f2(k0.z), U1.x); fmaf2(ac01, bf2f2(k0.w), U1.y);
                    fmaf2(ac10, bf2f2(k1.x), U0.x); fmaf2(ac11, bf2f2(k1.y), U0.y);
                    fmaf2(ac10, bf2f2(k1.z), U1.x); fmaf2(ac11, bf2f2(k1.w), U1.y);
                    k0 = nk0; k1 = nk1;
                }
                float2 q0 = upk2f(ac00), q1 = upk2f(ac01);
                float2 q2 = upk2f(ac10), q3 = upk2f(ac11);
                float s0 = (q0.x + q0.y) + (q1.x + q1.y);
                float s1 = (q2.x + q2.y) + (q3.x + q3.y);
                warpSum2F(s0, s1);
                if (lane == 0) {
                    bvg[cb] = ((cb < nc) ? b_in : b_last) / s0;
                    if (cb + 1 < C) bvg[cb + 1] = ((cb + 1 < nc) ? b_in : b_last) / s1;
                }
            }
            GBAR();
            if (it == ITS) break;

            // pass2: u = a / (K bv)
            for (int i4 = tid; i4 < (CPP >> 2); i4 += NT)
                ((float4*)sh)[i4] = __ldcg(bvg4 + i4);
            __syncthreads();
            for (int rb = gw * 2; rb < R; rb += GW * 2) {
                const int r1 = (rb + 1 < R) ? (rb + 1) : rb;
                const uint4* Kr0 = (const uint4*)(Kg + (size_t)rb * CPP);
                const uint4* Kr1 = (const uint4*)(Kg + (size_t)r1 * CPP);
                unsigned long long ac00 = 0, ac01 = 0, ac10 = 0, ac11 = 0;
                uint4 k0 = __ldcg(Kr0 + lane);
                uint4 k1 = __ldcg(Kr1 + lane);
                for (int sg = 0; sg < segB; sg++) {
                    const int nx = (sg + 1 < segB) ? (sg + 1) : sg;
                    uint4 nk0 = __ldcg(Kr0 + nx * 32 + lane);
                    uint4 nk1 = __ldcg(Kr1 + nx * 32 + lane);
                    ulonglong2 U0 = *(const ulonglong2*)(sh + sg * 256 + lane * 4);
                    ulonglong2 U1 = *(const ulonglong2*)(sh + sg * 256 + 128 + lane * 4);
                    fmaf2(ac00, bf2f2(k0.x), U0.x); fmaf2(ac01, bf2f2(k0.y), U0.y);
                    fmaf2(ac00, bf2f2(k0.z), U1.x); fmaf2(ac01, bf2f2(k0.w), U1.y);
                    fmaf2(ac10, bf2f2(k1.x), U0.x); fmaf2(ac11, bf2f2(k1.y), U0.y);
                    fmaf2(ac10, bf2f2(k1.z), U1.x); fmaf2(ac11, bf2f2(k1.w), U1.y);
                    k0 = nk0; k1 = nk1;
                }
                float2 q0 = upk2f(ac00), q1 = upk2f(ac01);
                float2 q2 = upk2f(ac10), q3 = upk2f(ac11);
                float s0 = (q0.x + q0.y) + (q1.x + q1.y);
                float s1 = (q2.x + q2.y) + (q3.x + q3.y);
                warpSum2F(s0, s1);
                if (lane == 0) {
                    ug[rb] = ((rb < nt) ? a_in : a_last) / s0;
                    if (rb + 1 < R) ug[rb + 1] = ((rb + 1 < nt) ? a_in : a_last) / s1;
                }
            }
            GBAR();
        }

        // ---------- Final: 2 * sum u_i K_ij v_j Mt_ij ----------
        {
            for (int i4 = tid; i4 < (CPP >> 2); i4 += NT)
                ((float4*)sh)[i4] = __ldcg(bvg4 + i4);
            __syncthreads();
            double wacc = 0.0;
            for (int r2 = gw; r2 < R; r2 += GW) {
                const uint4*  Kr = (const uint4*)(Kg + (size_t)r2 * CPP);
                const float4* Mr = (const float4*)(Mg + (size_t)r2 * CPP);
                const bool lastRow = (r2 == nt);
                float acc = 0.0f;
                for (int sg = 0; sg < segB; sg++) {
                    uint4 kv = __ldcg(Kr + sg * 32 + lane);
                    float4 m0 = __ldcg(Mr + sg * 64 + lane);
                    float4 m1 = __ldcg(Mr + sg * 64 + 32 + lane);
                    float4 vv0 = *(const float4*)(sh + sg * 256 + lane * 4);
                    float4 vv1 = *(const float4*)(sh + sg * 256 + 128 + lane * 4);
                    float2 f0 = upk2f(bf2f2(kv.x));
                    float2 f1 = upk2f(bf2f2(kv.y));
                    float2 f2 = upk2f(bf2f2(kv.z));
                    float2 f3 = upk2f(bf2f2(kv.w));
                    int j1 = sg * 256 + lane * 4;
                    int j2 = j1 + 128;
                    float mt[8];
                    if (lastRow) {
                        mt[0] = (j1+0 < nc) ? delta : 0.0f;
                        mt[1] = (j1+1 < nc) ? delta : 0.0f;
                        mt[2] = (j1+2 < nc) ? delta : 0.0f;
                        mt[3] = (j1+3 < nc) ? delta : 0.0f;
                        mt[4] = (j2+0 < nc) ? delta : 0.0f;
                        mt[5] = (j2+1 < nc) ? delta : 0.0f;
                        mt[6] = (j2+2 < nc) ? delta : 0.0f;
                        mt[7] = (j2+3 < nc) ? delta : 0.0f;
                    } else {
                        mt[0] = (j1+0 < nc) ? m0.x : ((j1+0 == nc) ? delta : 0.0f);
                        mt[1] = (j1+1 < nc) ? m0.y : ((j1+1 == nc) ? delta : 0.0f);
                        mt[2] = (j1+2 < nc) ? m0.z : ((j1+2 == nc) ? delta : 0.0f);
                        mt[3] = (j1+3 < nc) ? m0.w : ((j1+3 == nc) ? delta : 0.0f);
                        mt[4] = (j2+0 < nc) ? m1.x : ((j2+0 == nc) ? delta : 0.0f);
                        mt[5] = (j2+1 < nc) ? m1.y : ((j2+1 == nc) ? delta : 0.0f);
                        mt[6] = (j2+2 < nc) ? m1.z : ((j2+2 == nc) ? delta : 0.0f);
                        mt[7] = (j2+3 < nc) ? m1.w : ((j2+3 == nc) ? delta : 0.0f);
                    }
                    acc = fmaf(f0.x * vv0.x, mt[0], acc);
                    acc = fmaf(f0.y * vv0.y, mt[1], acc);
                    acc = fmaf(f1.x * vv0.z, mt[2], acc);
                    acc = fmaf(f1.y * vv0.w, mt[3], acc);
                    acc = fmaf(f2.x * vv1.x, mt[4], acc);
                    acc = fmaf(f2.y * vv1.y, mt[5], acc);
                    acc = fmaf(f3.x * vv1.z, mt[6], acc);
                    acc = fmaf(f3.y * vv1.w, mt[7], acc);
                }
                acc = warpSumF(acc);
                if (lane == 0) wacc += (double)(__ldcg(&ug[r2]) * acc);
            }
            __syncthreads();
            if (lane == 0) s_d[wid] = wacc;
            __syncthreads();
            if (wid == 0) {
                double t2 = warpSumD(s_d[lane]);
                if (lane == 0) g_pres[grp][lb] = t2;
            }
        }
        GBAR();
        if (lb == 0 && tid == 0) {
            double ts = 0.0;
            #pragma unroll 4
            for (int k2 = 0; k2 < GNB; k2++) ts += __ldcg(&g_pres[grp][k2]);
            g_res[s] = 2.0 * ts;
        }
    }

    // ---------------- global combine ----------------
    __threadfence();
    __syncthreads();
    if (tid == 0) atomicAdd(&g_doneCnt, 1ULL);
    if (bid == 0 && tid == 0) {
        unsigned long long tgt = doneBase + (unsigned long long)NB;
        while (*(volatile unsigned long long*)&g_doneCnt < tgt) { __nanosleep(128); }
        __threadfence();
        double total = 0.0;
        for (int s = 0; s < S_; s++) total += __ldcg(&g_res[s]);
        out[0] = (float)total;
    }
}

extern "C" void kernel_launch(void* const* d_in, const int* in_sizes, int n_in,
                              void* d_out, int out_size) {
    const float* X = (const float*)d_in[0];
    const int*   T = (const int*)d_in[1];
    float* out = (float*)d_out;
    (void)in_sizes; (void)n_in; (void)out_size;
    sinkhorn_all<<<NB, NT>>>(X, T, out);
}

// round 8
// speedup vs baseline: 1.5338x; 1.5338x over previous
#include <cuda_runtime.h>
#include <cuda_fp16.h>
#include <math.h>
#include <float.h>

#define NB 144          // total blocks (1 CTA/SM, 144 <= 148)
#define GROUPS 4        // independent groups
#define GNB 36          // blocks per group
#define SPG 8           // timesteps per group
#define NT 1024         // threads per block
#define N_ 4096
#define S_ 32
#define D_ 128
#define MAXP 4352       // worst-case padded dim bound (multiple of 256)
#define ITS 20
#define EPSK 1e-6f

// ---------------- persistent scratch (__device__ globals: allocation-free) ----------------
__device__ __align__(16) float  g_Xg[(size_t)S_ * N_ * D_];
__device__ float  g_nrm[S_ * N_];
__device__ __align__(16) float  g_M [(size_t)GROUPS * MAXP * MAXP];
__device__ __align__(16) __half g_K [(size_t)GROUPS * MAXP * MAXP];
__device__ __align__(16) __half g_KT[(size_t)GROUPS * MAXP * MAXP];
__device__ __align__(16) float  g_u [GROUPS][MAXP];
__device__ __align__(16) float  g_bv[GROUPS][MAXP];
__device__ int    g_perm[GROUPS][N_];
__device__ int    g_ntA [GROUPS];
__device__ float  g_pA  [GROUPS];
__device__ float  g_pmax[GROUPS][GNB];
__device__ double g_psum[GROUPS][GNB];
__device__ double g_pres[GROUPS][GNB];
__device__ double g_res [S_];
__device__ unsigned long long g_barCnt[GROUPS * 16];
__device__ unsigned long long g_doneCnt;

// ---------------- group barrier: monotonic 64-bit counter ----------------
__device__ __forceinline__ void gbar_sync(unsigned long long* cnt, unsigned long long tgt) {
    __syncthreads();
    if (threadIdx.x == 0) {
        __threadfence();
        atomicAdd(cnt, 1ULL);
        while (*(volatile unsigned long long*)cnt < tgt) { __nanosleep(32); }
        __threadfence();
    }
    __syncthreads();
}
#define GBAR() do { ++barK; gbar_sync(cntp, barBase + (unsigned long long)barK * GNB); } while (0)

// ---------------- FFMA-only expf ----------------
__device__ __forceinline__ float fast_exp(float x) {
    const float L2E = 1.4426950408889634f;
    float y = fmaf(x, L2E, 12582912.0f);
    int   n = __float_as_int(y) - 0x4B400000;
    float r = y - 12582912.0f;
    float f = fmaf(x, L2E, -r);
    float p =        1.540353040e-4f;
    p = fmaf(p, f,   1.333355815e-3f);
    p = fmaf(p, f,   9.618129107e-3f);
    p = fmaf(p, f,   5.550410866e-2f);
    p = fmaf(p, f,   2.402265070e-1f);
    p = fmaf(p, f,   6.931471806e-1f);
    p = fmaf(p, f,   1.0f);
    return p * __int_as_float((n + 127) << 23);
}

__device__ __forceinline__ float warpMaxF(float v) {
    #pragma unroll
    for (int o = 16; o; o >>= 1) v = fmaxf(v, __shfl_down_sync(0xffffffffu, v, o));
    return v;
}
__device__ __forceinline__ float warpSumF(float v) {
    #pragma unroll
    for (int o = 16; o; o >>= 1) v += __shfl_down_sync(0xffffffffu, v, o);
    return v;
}
__device__ __forceinline__ double warpSumD(double v) {
    #pragma unroll
    for (int o = 16; o; o >>= 1) v += __shfl_down_sync(0xffffffffu, v, o);
    return v;
}
__device__ __forceinline__ void warpSum2F(float& v0, float& v1) {
    #pragma unroll
    for (int o = 16; o; o >>= 1) {
        v0 += __shfl_down_sync(0xffffffffu, v0, o);
        v1 += __shfl_down_sync(0xffffffffu, v1, o);
    }
}

// ---------------- packed f32x2 FMA (PTX-only; used in GEMM) ----------------
__device__ __forceinline__ unsigned long long pk2f(float a, float b) {
    unsigned long long r;
    asm("mov.b64 %0, {%1, %2};" : "=l"(r) : "f"(a), "f"(b));
    return r;
}
__device__ __forceinline__ float2 upk2f(unsigned long long v) {
    float2 r;
    asm("mov.b64 {%0, %1}, %2;" : "=f"(r.x), "=f"(r.y) : "l"(v));
    return r;
}
__device__ __forceinline__ void fmaf2(unsigned long long& d, unsigned long long a, unsigned long long b) {
    asm("fma.rn.f32x2 %0, %1, %2, %0;" : "+l"(d) : "l"(a), "l"(b));
}

__global__ void __launch_bounds__(NT, 1)
sinkhorn_all(const float* __restrict__ X, const int* __restrict__ T, float* __restrict__ out)
{
    __shared__ __align__(16) float sh[8448];
    __shared__ float  s_f[32];
    __shared__ double s_d[32];
    __shared__ float  s_delta, s_efflam;

    const int tid  = threadIdx.x;
    const int bid  = blockIdx.x;
    const int lane = tid & 31;
    const int wid  = tid >> 5;
    const int grp  = bid / GNB;
    const int lb   = bid - grp * GNB;
    const int gw   = lb * 32 + wid;     // warp within group (0..GNB*32-1)
    const int GW   = GNB * 32;

    unsigned long long* cntp = &g_barCnt[grp * 16];
    unsigned long long v0 = *(volatile unsigned long long*)cntp;
    unsigned long long barBase = v0 - (v0 % (unsigned long long)GNB);
    int barK = 0;

    unsigned long long doneBase = 0;
    if (bid == 0 && tid == 0) {
        unsigned long long dv = *(volatile unsigned long long*)&g_doneCnt;
        doneBase = dv - (dv % (unsigned long long)NB);
    }

    float*  Mg  = g_M  + (size_t)grp * MAXP * MAXP;
    __half* Kg  = g_K  + (size_t)grp * MAXP * MAXP;
    __half* KTg = g_KT + (size_t)grp * MAXP * MAXP;
    float*  ug  = g_u [grp];
    float*  bvg = g_bv[grp];
    int*    permg = g_perm[grp];

    // ---------------- A0: stable permutation (per group) ----------------
    if (lb == 0) {
        int* cnt = (int*)sh;
        int base = tid * 4;
        int tv0 = T[base], tv1 = T[base+1], tv2 = T[base+2], tv3 = T[base+3];
        int c = (tv0 > 0) + (tv1 > 0) + (tv2 > 0) + (tv3 > 0);
        cnt[tid] = c;
        __syncthreads();
        for (int off = 1; off < NT; off <<= 1) {
            int vv  = cnt[tid];
            int add = (tid >= off) ? cnt[tid - off] : 0;
            __syncthreads();
            cnt[tid] = vv + add;
            __syncthreads();
        }
        int total = cnt[NT - 1];
        int excl  = cnt[tid] - c;
        int tpos = excl, cpos = total + base - excl;
        if (tv0 > 0) permg[tpos++] = base + 0; else permg[cpos++] = base + 0;
        if (tv1 > 0) permg[tpos++] = base + 1; else permg[cpos++] = base + 1;
        if (tv2 > 0) permg[tpos++] = base + 2; else permg[cpos++] = base + 2;
        if (tv3 > 0) permg[tpos++] = base + 3; else permg[cpos++] = base + 3;
        if (tid == NT - 1) { g_ntA[grp] = total; g_pA[grp] = (float)total / (float)N_; }
    }
    GBAR();

    const int   nt = g_ntA[grp];
    const int   nc = N_ - nt;
    const float p  = g_pA[grp];
    const int   R = nt + 1, C = nc + 1;
    const int   RPP = (R + 255) & ~255;
    const int   CPP = (C + 255) & ~255;
    const float a_in = p / (float)nt, a_last = 1.0f - p;
    const float b_in = (1.0f - p) / (float)nc, b_last = p;

    // ---------------- A1: gather 8 timesteps + squared norms ----------------
    for (int job = gw; job < SPG * N_; job += GW) {
        int s = grp * SPG + (job >> 12);
        int r = job & (N_ - 1);
        int src = permg[r];
        const float4* sp = (const float4*)(X + ((size_t)src * S_ + s) * D_);
        float4 vv = sp[lane];
        ((float4*)(g_Xg + ((size_t)s * N_ + r) * D_))[lane] = vv;
        float sq = vv.x*vv.x + vv.y*vv.y + vv.z*vv.z + vv.w*vv.w;
        sq = warpSumF(sq);
        if (lane == 0) g_nrm[s * N_ + r] = sq;
    }
    GBAR();

    // ================== per-timestep loop ==================
    for (int sl = 0; sl < SPG; sl++) {
        const int s = grp * SPG + sl;
        const float* Xt  = g_Xg + (size_t)s * N_ * D_;
        const float* nrm = g_nrm + s * N_;

        // ---------- B1: M = nx + ny - 2*Xt*Xc^T (128x128 tiles, 4x4/thread, f32x2) ----------
        {
            float* As = sh;
            float* Bs = sh + 4096;
            const int tilesI = (nt + 127) >> 7;
            const int tilesJ = (nc + 127) >> 7;
            const int nTiles = tilesI * tilesJ;
            const int lrow = tid & 127;
            const int ld4  = tid >> 7;
            const int tx = lane;
            const int ty = wid;
            float  lmax = -FLT_MAX;
            double lsum = 0.0;

            for (int tile = lb; tile < nTiles; tile += GNB) {
                int ti = tile / tilesJ, tj = tile - ti * tilesJ;
                int i0 = ti << 7, j0 = tj << 7;
                int arow = i0 + lrow; if (arow >= nt) arow = nt - 1;
                int brow = j0 + lrow; if (brow >= nc) brow = nc - 1;
                const float* ap = Xt + (size_t)arow * D_ + ld4 * 4;
                const float* bp = Xt + (size_t)(nt + brow) * D_ + ld4 * 4;

                unsigned long long acc2[4][2] = {};

                for (int d0 = 0; d0 < D_; d0 += 32) {
                    __syncthreads();
                    float4 av = *(const float4*)(ap + d0);
                    float4 bw = *(const float4*)(bp + d0);
                    int dd0 = ld4 * 4;
                    As[(dd0+0)*128 + lrow] = av.x;  As[(dd0+1)*128 + lrow] = av.y;
                    As[(dd0+2)*128 + lrow] = av.z;  As[(dd0+3)*128 + lrow] = av.w;
                    Bs[(dd0+0)*128 + lrow] = bw.x;  Bs[(dd0+1)*128 + lrow] = bw.y;
                    Bs[(dd0+2)*128 + lrow] = bw.z;  Bs[(dd0+3)*128 + lrow] = bw.w;
                    __syncthreads();
                    #pragma unroll
                    for (int dd = 0; dd < 32; dd++) {
                        float4 a4 = *(const float4*)&As[dd*128 + ty*4];
                        ulonglong2 b2 = *(const ulonglong2*)&Bs[dd*128 + tx*4];
                        unsigned long long ax = pk2f(a4.x, a4.x);
                        unsigned long long ay = pk2f(a4.y, a4.y);
                        unsigned long long az = pk2f(a4.z, a4.z);
                        unsigned long long aw = pk2f(a4.w, a4.w);
                        fmaf2(acc2[0][0], ax, b2.x); fmaf2(acc2[0][1], ax, b2.y);
                        fmaf2(acc2[1][0], ay, b2.x); fmaf2(acc2[1][1], ay, b2.y);
                        fmaf2(acc2[2][0], az, b2.x); fmaf2(acc2[2][1], az, b2.y);
                        fmaf2(acc2[3][0], aw, b2.x); fmaf2(acc2[3][1], aw, b2.y);
                    }
                }
                float tsum = 0.0f;
                #pragma unroll
                for (int rr = 0; rr < 4; rr++) {
                    int i = i0 + ty * 4 + rr;
                    if (i >= nt) break;
                    float nx = nrm[i];
                    float2 c01 = upk2f(acc2[rr][0]);
                    float2 c23 = upk2f(acc2[rr][1]);
                    float cv[4] = { c01.x, c01.y, c23.x, c23.y };
                    #pragma unroll
                    for (int cc = 0; cc < 4; cc++) {
                        int j = j0 + tx * 4 + cc;
                        if (j >= nc) break;
                        float m = fmaf(-2.0f, cv[cc], nx + nrm[nt + j]);
                        Mg[(size_t)i * CPP + j] = m;
                        lmax = fmaxf(lmax, m);
                        tsum += m;
                    }
                }
                lsum += (double)tsum;
            }
            lmax = warpMaxF(lmax);
            lsum = warpSumD(lsum);
            __syncthreads();
            if (lane == 0) { s_f[wid] = lmax; s_d[wid] = lsum; }
            __syncthreads();
            if (wid == 0) {
                float  m2 = s_f[lane];
                double s2 = s_d[lane];
                m2 = warpMaxF(m2);
                s2 = warpSumD(s2);
                if (lane == 0) { g_pmax[grp][lb] = m2; g_psum[grp][lb] = s2; }
            }
        }
        GBAR();

        // ---------- B2: reduce GNB partials (identical fixed order in every block) ----------
        if (tid == 0) {
            float  dmax = -FLT_MAX;
            double dsum = 0.0;
            #pragma unroll 6
            for (int k2 = 0; k2 < GNB; k2++) {
                dmax = fmaxf(dmax, __ldcg(&g_pmax[grp][k2]));
                dsum += __ldcg(&g_psum[grp][k2]);
            }
            s_delta  = dmax;
            s_efflam = (float)(((double)nt * (double)nc) / dsum);
        }
        __syncthreads();
        const float delta  = s_delta;
        const float efflam = s_efflam;

        // ---------- B3: K = exp(-efflam*Mt)+eps (fp16, segment-permuted), K^T transpose ----------
        {
            const int rowStrips = RPP >> 5, colStrips = CPP >> 7;
            const int nStr = rowStrips * colStrips;
            const int srow = wid;
            const int tj = tid >> 3;
            const int io = (tid & 7) * 4;
            const float kdelta = fast_exp(-efflam * delta) + EPSK;

            for (int str = lb; str < nStr; str += GNB) {
                int sr = str / colStrips, sc = str - sr * colStrips;
                int i0 = sr << 5, j0 = sc << 7;
                int i = i0 + srow;
                float kq[4];
                #pragma unroll
                for (int q = 0; q < 4; q++) {
                    int j = j0 + lane * 4 + q;
                    float kv;
                    if (i < nt && j < nc) {
                        float m = __ldcg(&Mg[(size_t)i * CPP + j]);
                        kv = fast_exp(-efflam * m) + EPSK;
                    } else if (i == nt && j < nc) kv = kdelta;
                    else if (j == nc && i < nt)   kv = kdelta;
                    else if (i == nt && j == nc)  kv = 1.0f + EPSK;
                    else                          kv = 0.0f;
                    kq[q] = kv;
                }
                *(float4*)&sh[srow * 132 + lane * 4] = make_float4(kq[0], kq[1], kq[2], kq[3]);
                {
                    union { __half2 h[2]; uint2 u; } cv;
                    cv.h[0] = __floats2half2_rn(kq[0], kq[1]);
                    cv.h[1] = __floats2half2_rn(kq[2], kq[3]);
                    int halfOff = (j0 & ~255) + lane * 8 + ((j0 & 128) ? 4 : 0);
                    *(uint2*)&Kg[(size_t)i * CPP + halfOff] = cv.u;
                }
                __syncthreads();
                {
                    union { __half2 h[2]; uint2 u; } cv;
                    cv.h[0] = __floats2half2_rn(sh[(io+0)*132 + tj], sh[(io+1)*132 + tj]);
                    cv.h[1] = __floats2half2_rn(sh[(io+2)*132 + tj], sh[(io+3)*132 + tj]);
                    int ii = i0 + io;
                    int halfOff = (ii & ~255) + ((ii & 127) >> 2) * 8 + ((ii & 128) ? 4 : 0);
                    *(uint2*)&KTg[(size_t)(j0 + tj) * RPP + halfOff] = cv.u;
                }
                __syncthreads();
            }
            if (lb == 0) {
                for (int r2 = tid; r2 < RPP; r2 += NT)
                    ug[r2] = (r2 < nt) ? a_in : ((r2 == nt) ? a_last : 0.0f);
                for (int c2 = tid; c2 < CPP; c2 += NT)
                    if (c2 >= C) bvg[c2] = 0.0f;
            }
        }
        GBAR();

        // ---------- Sinkhorn: 20 iterations + final v pass ----------
        const int segU = RPP >> 8;
        const int segB = CPP >> 8;
        const float4* ug4  = (const float4*)ug;
        const float4* bvg4 = (const float4*)bvg;

        for (int it = 0; it <= ITS; it++) {
            // pass1: bv = b / (K^T u)  (u staged in smem, conflict-free permuted layout)
            for (int i4 = tid; i4 < (RPP >> 2); i4 += NT)
                ((float4*)sh)[i4] = __ldcg(ug4 + i4);
            __syncthreads();
            for (int cb = gw * 2; cb < C; cb += GW * 2) {
                const int c1 = (cb + 1 < C) ? (cb + 1) : cb;
                const uint4* Kr0 = (const uint4*)(KTg + (size_t)cb * RPP);
                const uint4* Kr1 = (const uint4*)(KTg + (size_t)c1 * RPP);
                float a00 = 0, a01 = 0, a10 = 0, a11 = 0;
                for (int sg = 0; sg < segU; sg++) {
                    uint4 k0 = __ldcg(Kr0 + sg * 32 + lane);
                    uint4 k1 = __ldcg(Kr1 + sg * 32 + lane);
                    float4 u0 = *(const float4*)&sh[sg * 256 + lane * 4];
                    float4 u1 = *(const float4*)&sh[sg * 256 + 128 + lane * 4];
                    const __half2* h0 = (const __half2*)&k0;
                    const __half2* h1 = (const __half2*)&k1;
                    float2 p00 = __half22float2(h0[0]), p01 = __half22float2(h0[1]);
                    float2 p02 = __half22float2(h0[2]), p03 = __half22float2(h0[3]);
                    float2 p10 = __half22float2(h1[0]), p11 = __half22float2(h1[1]);
                    float2 p12 = __half22float2(h1[2]), p13 = __half22float2(h1[3]);
                    a00 = fmaf(p00.x, u0.x, a00); a01 = fmaf(p00.y, u0.y, a01);
                    a00 = fmaf(p01.x, u0.z, a00); a01 = fmaf(p01.y, u0.w, a01);
                    a00 = fmaf(p02.x, u1.x, a00); a01 = fmaf(p02.y, u1.y, a01);
                    a00 = fmaf(p03.x, u1.z, a00); a01 = fmaf(p03.y, u1.w, a01);
                    a10 = fmaf(p10.x, u0.x, a10); a11 = fmaf(p10.y, u0.y, a11);
                    a10 = fmaf(p11.x, u0.z, a10); a11 = fmaf(p11.y, u0.w, a11);
                    a10 = fmaf(p12.x, u1.x, a10); a11 = fmaf(p12.y, u1.y, a11);
                    a10 = fmaf(p13.x, u1.z, a10); a11 = fmaf(p13.y, u1.w, a11);
                }
                float s0 = a00 + a01, s1 = a10 + a11;
                warpSum2F(s0, s1);
                if (lane == 0) {
                    bvg[cb] = ((cb < nc) ? b_in : b_last) / s0;
                    if (cb + 1 < C) bvg[cb + 1] = ((cb + 1 < nc) ? b_in : b_last) / s1;
                }
            }
            GBAR();
            if (it == ITS) break;

            // pass2: u = a / (K bv)
            for (int i4 = tid; i4 < (CPP >> 2); i4 += NT)
                ((float4*)sh)[i4] = __ldcg(bvg4 + i4);
            __syncthreads();
            for (int rb = gw * 2; rb < R; rb += GW * 2) {
                const int r1 = (rb + 1 < R) ? (rb + 1) : rb;
                const uint4* Kr0 = (const uint4*)(Kg + (size_t)rb * CPP);
                const uint4* Kr1 = (const uint4*)(Kg + (size_t)r1 * CPP);
                float a00 = 0, a01 = 0, a10 = 0, a11 = 0;
                for (int sg = 0; sg < segB; sg++) {
                    uint4 k0 = __ldcg(Kr0 + sg * 32 + lane);
                    uint4 k1 = __ldcg(Kr1 + sg * 32 + lane);
                    float4 u0 = *(const float4*)&sh[sg * 256 + lane * 4];
                    float4 u1 = *(const float4*)&sh[sg * 256 + 128 + lane * 4];
                    const __half2* h0 = (const __half2*)&k0;
                    const __half2* h1 = (const __half2*)&k1;
                    float2 p00 = __half22float2(h0[0]), p01 = __half22float2(h0[1]);
                    float2 p02 = __half22float2(h0[2]), p03 = __half22float2(h0[3]);
                    float2 p10 = __half22float2(h1[0]), p11 = __half22float2(h1[1]);
                    float2 p12 = __half22float2(h1[2]), p13 = __half22float2(h1[3]);
                    a00 = fmaf(p00.x, u0.x, a00); a01 = fmaf(p00.y, u0.y, a01);
                    a00 = fmaf(p01.x, u0.z, a00); a01 = fmaf(p01.y, u0.w, a01);
                    a00 = fmaf(p02.x, u1.x, a00); a01 = fmaf(p02.y, u1.y, a01);
                    a00 = fmaf(p03.x, u1.z, a00); a01 = fmaf(p03.y, u1.w, a01);
                    a10 = fmaf(p10.x, u0.x, a10); a11 = fmaf(p10.y, u0.y, a11);
                    a10 = fmaf(p11.x, u0.z, a10); a11 = fmaf(p11.y, u0.w, a11);
                    a10 = fmaf(p12.x, u1.x, a10); a11 = fmaf(p12.y, u1.y, a11);
                    a10 = fmaf(p13.x, u1.z, a10); a11 = fmaf(p13.y, u1.w, a11);
                }
                float s0 = a00 + a01, s1 = a10 + a11;
                warpSum2F(s0, s1);
                if (lane == 0) {
                    ug[rb] = ((rb < nt) ? a_in : a_last) / s0;
                    if (rb + 1 < R) ug[rb + 1] = ((rb + 1 < nt) ? a_in : a_last) / s1;
                }
            }
            GBAR();
        }

        // ---------- Final: 2 * sum u_i K_ij v_j Mt_ij ----------
        {
            for (int i4 = tid; i4 < (CPP >> 2); i4 += NT)
                ((float4*)sh)[i4] = __ldcg(bvg4 + i4);
            __syncthreads();
            double wacc = 0.0;
            for (int r2 = gw; r2 < R; r2 += GW) {
                const uint4*  Kr = (const uint4*)(Kg + (size_t)r2 * CPP);
                const float4* Mr = (const float4*)(Mg + (size_t)r2 * CPP);
                const bool lastRow = (r2 == nt);
                float acc = 0.0f;
                for (int sg = 0; sg < segB; sg++) {
                    uint4 kv = __ldcg(Kr + sg * 32 + lane);
                    const __half2* hp = (const __half2*)&kv;
                    float4 m0 = __ldcg(Mr + sg * 64 + lane);
                    float4 m1 = __ldcg(Mr + sg * 64 + 32 + lane);
                    float4 vv0 = *(const float4*)&sh[sg * 256 + lane * 4];
                    float4 vv1 = *(const float4*)&sh[sg * 256 + 128 + lane * 4];
                    float2 f0 = __half22float2(hp[0]);
                    float2 f1 = __half22float2(hp[1]);
                    float2 f2 = __half22float2(hp[2]);
                    float2 f3 = __half22float2(hp[3]);
                    int j1 = sg * 256 + lane * 4;
                    int j2 = j1 + 128;
                    float mt[8];
                    if (lastRow) {
                        mt[0] = (j1+0 < nc) ? delta : 0.0f;
                        mt[1] = (j1+1 < nc) ? delta : 0.0f;
                        mt[2] = (j1+2 < nc) ? delta : 0.0f;
                        mt[3] = (j1+3 < nc) ? delta : 0.0f;
                        mt[4] = (j2+0 < nc) ? delta : 0.0f;
                        mt[5] = (j2+1 < nc) ? delta : 0.0f;
                        mt[6] = (j2+2 < nc) ? delta : 0.0f;
                        mt[7] = (j2+3 < nc) ? delta : 0.0f;
                    } else {
                        mt[0] = (j1+0 < nc) ? m0.x : ((j1+0 == nc) ? delta : 0.0f);
                        mt[1] = (j1+1 < nc) ? m0.y : ((j1+1 == nc) ? delta : 0.0f);
                        mt[2] = (j1+2 < nc) ? m0.z : ((j1+2 == nc) ? delta : 0.0f);
                        mt[3] = (j1+3 < nc) ? m0.w : ((j1+3 == nc) ? delta : 0.0f);
                        mt[4] = (j2+0 < nc) ? m1.x : ((j2+0 == nc) ? delta : 0.0f);
                        mt[5] = (j2+1 < nc) ? m1.y : ((j2+1 == nc) ? delta : 0.0f);
                        mt[6] = (j2+2 < nc) ? m1.z : ((j2+2 == nc) ? delta : 0.0f);
                        mt[7] = (j2+3 < nc) ? m1.w : ((j2+3 == nc) ? delta : 0.0f);
                    }
                    acc = fmaf(f0.x * vv0.x, mt[0], acc);
                    acc = fmaf(f0.y * vv0.y, mt[1], acc);
                    acc = fmaf(f1.x * vv0.z, mt[2], acc);
                    acc = fmaf(f1.y * vv0.w, mt[3], acc);
                    acc = fmaf(f2.x * vv1.x, mt[4], acc);
                    acc = fmaf(f2.y * vv1.y, mt[5], acc);
                    acc = fmaf(f3.x * vv1.z, mt[6], acc);
                    acc = fmaf(f3.y * vv1.w, mt[7], acc);
                }
                acc = warpSumF(acc);
                if (lane == 0) wacc += (double)(__ldcg(&ug[r2]) * acc);
            }
            __syncthreads();
            if (lane == 0) s_d[wid] = wacc;
            __syncthreads();
            if (wid == 0) {
                double t2 = warpSumD(s_d[lane]);
                if (lane == 0) g_pres[grp][lb] = t2;
            }
        }
        GBAR();
        if (lb == 0 && tid == 0) {
            double ts = 0.0;
            #pragma unroll 6
            for (int k2 = 0; k2 < GNB; k2++) ts += __ldcg(&g_pres[grp][k2]);
            g_res[s] = 2.0 * ts;
        }
    }

    // ---------------- global combine ----------------
    __threadfence();
    __syncthreads();
    if (tid == 0) atomicAdd(&g_doneCnt, 1ULL);
    if (bid == 0 && tid == 0) {
        unsigned long long tgt = doneBase + (unsigned long long)NB;
        while (*(volatile unsigned long long*)&g_doneCnt < tgt) { __nanosleep(128); }
        __threadfence();
        double total = 0.0;
        for (int s = 0; s < S_; s++) total += __ldcg(&g_res[s]);
        out[0] = (float)total;
    }
}

extern "C" void kernel_launch(void* const* d_in, const int* in_sizes, int n_in,
                              void* d_out, int out_size) {
    const float* X = (const float*)d_in[0];
    const int*   T = (const int*)d_in[1];
    float* out = (float*)d_out;
    (void)in_sizes; (void)n_in; (void)out_size;
    sinkhorn_all<<<NB, NT>>>(X, T, out);
}

// round 9
// speedup vs baseline: 1.9928x; 1.2992x over previous
#include <cuda_runtime.h>
#include <cuda_fp16.h>
#include <cuda_bf16.h>
#include <math.h>
#include <float.h>

#define NB 144          // total blocks (1 CTA/SM, 144 <= 148)
#define GROUPS 4        // independent groups
#define GNB 36          // blocks per group
#define SPG 8           // timesteps per group
#define NT 1024         // threads per block
#define N_ 4096
#define S_ 32
#define D_ 128
#define MAXP 4352       // worst-case padded dim bound (multiple of 256)
#define ITS 20
#define EPSK 1e-6f
#define SMEM_BYTES 73728   // 4 tiles x 128 rows x 72 halves x 2B

// ---------------- persistent scratch (__device__ globals: allocation-free) ----------------
__device__ __align__(16) __nv_bfloat16 g_Xh[(size_t)S_ * N_ * D_];   // hi part of permuted X
__device__ __align__(16) __nv_bfloat16 g_Xl[(size_t)S_ * N_ * D_];   // lo part
__device__ float  g_nrm[S_ * N_];
__device__ __align__(16) float  g_M [(size_t)GROUPS * MAXP * MAXP];
__device__ __align__(16) __half g_K [(size_t)GROUPS * MAXP * MAXP];
__device__ __align__(16) __half g_KT[(size_t)GROUPS * MAXP * MAXP];
__device__ __align__(16) float  g_u [GROUPS][MAXP];
__device__ __align__(16) float  g_bv[GROUPS][MAXP];
__device__ int    g_perm[GROUPS][N_];
__device__ int    g_ntA [GROUPS];
__device__ float  g_pA  [GROUPS];
__device__ float  g_pmax[GROUPS][GNB];
__device__ double g_psum[GROUPS][GNB];
__device__ double g_pres[GROUPS][GNB];
__device__ double g_res [S_];
__device__ unsigned long long g_barCnt[GROUPS * 16];
__device__ unsigned long long g_doneCnt;

// ---------------- group barrier: monotonic 64-bit counter ----------------
__device__ __forceinline__ void gbar_sync(unsigned long long* cnt, unsigned long long tgt) {
    __syncthreads();
    if (threadIdx.x == 0) {
        __threadfence();
        atomicAdd(cnt, 1ULL);
        while (*(volatile unsigned long long*)cnt < tgt) { __nanosleep(32); }
        __threadfence();
    }
    __syncthreads();
}
#define GBAR() do { ++barK; gbar_sync(cntp, barBase + (unsigned long long)barK * GNB); } while (0)

// ---------------- FFMA-only expf ----------------
__device__ __forceinline__ float fast_exp(float x) {
    const float L2E = 1.4426950408889634f;
    float y = fmaf(x, L2E, 12582912.0f);
    int   n = __float_as_int(y) - 0x4B400000;
    float r = y - 12582912.0f;
    float f = fmaf(x, L2E, -r);
    float p =        1.540353040e-4f;
    p = fmaf(p, f,   1.333355815e-3f);
    p = fmaf(p, f,   9.618129107e-3f);
    p = fmaf(p, f,   5.550410866e-2f);
    p = fmaf(p, f,   2.402265070e-1f);
    p = fmaf(p, f,   6.931471806e-1f);
    p = fmaf(p, f,   1.0f);
    return p * __int_as_float((n + 127) << 23);
}

__device__ __forceinline__ float warpMaxF(float v) {
    #pragma unroll
    for (int o = 16; o; o >>= 1) v = fmaxf(v, __shfl_down_sync(0xffffffffu, v, o));
    return v;
}
__device__ __forceinline__ float warpSumF(float v) {
    #pragma unroll
    for (int o = 16; o; o >>= 1) v += __shfl_down_sync(0xffffffffu, v, o);
    return v;
}
__device__ __forceinline__ double warpSumD(double v) {
    #pragma unroll
    for (int o = 16; o; o >>= 1) v += __shfl_down_sync(0xffffffffu, v, o);
    return v;
}
__device__ __forceinline__ void warpSum2F(float& v0, float& v1) {
    #pragma unroll
    for (int o = 16; o; o >>= 1) {
        v0 += __shfl_down_sync(0xffffffffu, v0, o);
        v1 += __shfl_down_sync(0xffffffffu, v1, o);
    }
}

// ---------------- mma.sync m16n8k16 bf16 (fp32 accum) ----------------
__device__ __forceinline__ void mma16816(float& c0, float& c1, float& c2, float& c3,
                                         unsigned a0, unsigned a1, unsigned a2, unsigned a3,
                                         unsigned b0, unsigned b1) {
    asm volatile("mma.sync.aligned.m16n8k16.row.col.f32.bf16.bf16.f32 "
        "{%0,%1,%2,%3}, {%4,%5,%6,%7}, {%8,%9}, {%0,%1,%2,%3};"
        : "+f"(c0), "+f"(c1), "+f"(c2), "+f"(c3)
        : "r"(a0), "r"(a1), "r"(a2), "r"(a3), "r"(b0), "r"(b1));
}

#define LDH 72   // padded smem row stride in halves (144B: conflict-free frag loads)

__global__ void __launch_bounds__(NT, 1)
sinkhorn_all(const float* __restrict__ X, const int* __restrict__ T, float* __restrict__ out)
{
    extern __shared__ __align__(16) char smraw[];
    float* sh = (float*)smraw;
    __nv_bfloat16* Ah = (__nv_bfloat16*)smraw;          // 128 x LDH
    __nv_bfloat16* Al = Ah + 128 * LDH;
    __nv_bfloat16* Bh = Al + 128 * LDH;
    __nv_bfloat16* Bl = Bh + 128 * LDH;

    __shared__ float  s_f[32];
    __shared__ double s_d[32];
    __shared__ float  s_delta, s_efflam;

    const int tid  = threadIdx.x;
    const int bid  = blockIdx.x;
    const int lane = tid & 31;
    const int wid  = tid >> 5;
    const int grp  = bid / GNB;
    const int lb   = bid - grp * GNB;
    const int gw   = lb * 32 + wid;     // warp within group
    const int GW   = GNB * 32;

    unsigned long long* cntp = &g_barCnt[grp * 16];
    unsigned long long v0 = *(volatile unsigned long long*)cntp;
    unsigned long long barBase = v0 - (v0 % (unsigned long long)GNB);
    int barK = 0;

    unsigned long long doneBase = 0;
    if (bid == 0 && tid == 0) {
        unsigned long long dv = *(volatile unsigned long long*)&g_doneCnt;
        doneBase = dv - (dv % (unsigned long long)NB);
    }

    float*  Mg  = g_M  + (size_t)grp * MAXP * MAXP;
    __half* Kg  = g_K  + (size_t)grp * MAXP * MAXP;
    __half* KTg = g_KT + (size_t)grp * MAXP * MAXP;
    float*  ug  = g_u [grp];
    float*  bvg = g_bv[grp];
    int*    permg = g_perm[grp];

    // ---------------- A0: stable permutation (per group) ----------------
    if (lb == 0) {
        int* cnt = (int*)sh;
        int base = tid * 4;
        int tv0 = T[base], tv1 = T[base+1], tv2 = T[base+2], tv3 = T[base+3];
        int c = (tv0 > 0) + (tv1 > 0) + (tv2 > 0) + (tv3 > 0);
        cnt[tid] = c;
        __syncthreads();
        for (int off = 1; off < NT; off <<= 1) {
            int vv  = cnt[tid];
            int add = (tid >= off) ? cnt[tid - off] : 0;
            __syncthreads();
            cnt[tid] = vv + add;
            __syncthreads();
        }
        int total = cnt[NT - 1];
        int excl  = cnt[tid] - c;
        int tpos = excl, cpos = total + base - excl;
        if (tv0 > 0) permg[tpos++] = base + 0; else permg[cpos++] = base + 0;
        if (tv1 > 0) permg[tpos++] = base + 1; else permg[cpos++] = base + 1;
        if (tv2 > 0) permg[tpos++] = base + 2; else permg[cpos++] = base + 2;
        if (tv3 > 0) permg[tpos++] = base + 3; else permg[cpos++] = base + 3;
        if (tid == NT - 1) { g_ntA[grp] = total; g_pA[grp] = (float)total / (float)N_; }
    }
    GBAR();

    const int   nt = g_ntA[grp];
    const int   nc = N_ - nt;
    const float p  = g_pA[grp];
    const int   R = nt + 1, C = nc + 1;
    const int   RPP = (R + 255) & ~255;
    const int   CPP = (C + 255) & ~255;
    const float a_in = p / (float)nt, a_last = 1.0f - p;
    const float b_in = (1.0f - p) / (float)nc, b_last = p;

    // ---------------- A1: gather 8 timesteps as bf16 hi/lo + fp32 squared norms ----------------
    for (int job = gw; job < SPG * N_; job += GW) {
        int s = grp * SPG + (job >> 12);
        int r = job & (N_ - 1);
        int src = permg[r];
        const float4* sp = (const float4*)(X + ((size_t)src * S_ + s) * D_);
        float4 vv = sp[lane];
        __nv_bfloat16 h0 = __float2bfloat16_rn(vv.x);
        __nv_bfloat16 h1 = __float2bfloat16_rn(vv.y);
        __nv_bfloat16 h2 = __float2bfloat16_rn(vv.z);
        __nv_bfloat16 h3 = __float2bfloat16_rn(vv.w);
        __nv_bfloat16 l0 = __float2bfloat16_rn(vv.x - __bfloat162float(h0));
        __nv_bfloat16 l1 = __float2bfloat16_rn(vv.y - __bfloat162float(h1));
        __nv_bfloat16 l2 = __float2bfloat16_rn(vv.z - __bfloat162float(h2));
        __nv_bfloat16 l3 = __float2bfloat16_rn(vv.w - __bfloat162float(h3));
        size_t off = ((size_t)s * N_ + r) * D_ + lane * 4;
        union { __nv_bfloat16 b[4]; uint2 u; } ph, pl;
        ph.b[0] = h0; ph.b[1] = h1; ph.b[2] = h2; ph.b[3] = h3;
        pl.b[0] = l0; pl.b[1] = l1; pl.b[2] = l2; pl.b[3] = l3;
        *(uint2*)(g_Xh + off) = ph.u;
        *(uint2*)(g_Xl + off) = pl.u;
        float sq = vv.x*vv.x + vv.y*vv.y + vv.z*vv.z + vv.w*vv.w;
        sq = warpSumF(sq);
        if (lane == 0) g_nrm[s * N_ + r] = sq;
    }
    GBAR();

    // ================== per-timestep loop ==================
    for (int sl = 0; sl < SPG; sl++) {
        const int s = grp * SPG + sl;
        const float* nrm = g_nrm + s * N_;
        const __nv_bfloat16* Xhs = g_Xh + (size_t)s * N_ * D_;
        const __nv_bfloat16* Xls = g_Xl + (size_t)s * N_ * D_;

        // ---------- B1: M = nx + ny - 2*(hi.hi + hi.lo + lo.hi) via mma.sync ----------
        {
            const int tilesI = (nt + 127) >> 7;
            const int tilesJ = (nc + 127) >> 7;
            const int nTiles = tilesI * tilesJ;
            const int wm = wid >> 2;          // 0..7 : m-offset wm*16
            const int wn = wid & 3;           // 0..3 : n-offset wn*32
            const int ldrow = tid >> 3;       // 0..127 : load row
            const int ldch  = tid & 7;        // 0..7  : 16B chunk
            float  lmax = -FLT_MAX;
            double lsum = 0.0;

            for (int tile = lb; tile < nTiles; tile += GNB) {
                int ti = tile / tilesJ, tj = tile - ti * tilesJ;
                int i0 = ti << 7, j0 = tj << 7;

                float acc[4][4];
                #pragma unroll
                for (int q = 0; q < 4; q++)
                    #pragma unroll
                    for (int c = 0; c < 4; c++) acc[q][c] = 0.0f;

                for (int kb = 0; kb < D_; kb += 64) {
                    __syncthreads();
                    {   // load 4 tiles: 1 uint4 each per thread, 144B padded rows
                        int ar = i0 + ldrow; if (ar >= nt) ar = nt - 1;
                        int br = j0 + ldrow; if (br >= nc) br = nc - 1;
                        size_t aoff = ((size_t)ar) * D_ + kb + ldch * 8;
                        size_t boff = ((size_t)(nt + br)) * D_ + kb + ldch * 8;
                        uint4 vah = *(const uint4*)(Xhs + aoff);
                        uint4 val = *(const uint4*)(Xls + aoff);
                        uint4 vbh = *(const uint4*)(Xhs + boff);
                        uint4 vbl = *(const uint4*)(Xls + boff);
                        int sm = ldrow * LDH + ldch * 8;
                        *(uint4*)&Ah[sm] = vah;
                        *(uint4*)&Al[sm] = val;
                        *(uint4*)&Bh[sm] = vbh;
                        *(uint4*)&Bl[sm] = vbl;
                    }
                    __syncthreads();
                    #pragma unroll
                    for (int ks = 0; ks < 4; ks++) {
                        const int k0 = ks * 16;
                        const int arow = wm * 16 + (lane >> 2);
                        const int ac   = k0 + (lane & 3) * 2;
                        unsigned ah0 = *(const unsigned*)&Ah[arow * LDH + ac];
                        unsigned ah1 = *(const unsigned*)&Ah[(arow + 8) * LDH + ac];
                        unsigned ah2 = *(const unsigned*)&Ah[arow * LDH + ac + 8];
                        unsigned ah3 = *(const unsigned*)&Ah[(arow + 8) * LDH + ac + 8];
                        unsigned al0 = *(const unsigned*)&Al[arow * LDH + ac];
                        unsigned al1 = *(const unsigned*)&Al[(arow + 8) * LDH + ac];
                        unsigned al2 = *(const unsigned*)&Al[arow * LDH + ac + 8];
                        unsigned al3 = *(const unsigned*)&Al[(arow + 8) * LDH + ac + 8];
                        #pragma unroll
                        for (int q = 0; q < 4; q++) {
                            const int bn = wn * 32 + q * 8 + (lane >> 2);
                            unsigned bh0 = *(const unsigned*)&Bh[bn * LDH + ac];
                            unsigned bh1 = *(const unsigned*)&Bh[bn * LDH + ac + 8];
                            unsigned bl0 = *(const unsigned*)&Bl[bn * LDH + ac];
                            unsigned bl1 = *(const unsigned*)&Bl[bn * LDH + ac + 8];
                            mma16816(acc[q][0], acc[q][1], acc[q][2], acc[q][3],
                                     ah0, ah1, ah2, ah3, bh0, bh1);
                            mma16816(acc[q][0], acc[q][1], acc[q][2], acc[q][3],
                                     ah0, ah1, ah2, ah3, bl0, bl1);
                            mma16816(acc[q][0], acc[q][1], acc[q][2], acc[q][3],
                                     al0, al1, al2, al3, bh0, bh1);
                        }
                    }
                }

                // epilogue: M = nx + ny - 2*dot; track max + sum
                float tsum = 0.0f;
                const int er0 = i0 + wm * 16 + (lane >> 2);
                #pragma unroll
                for (int half = 0; half < 2; half++) {
                    const int rr = er0 + half * 8;
                    if (rr >= nt) continue;
                    const float nx = nrm[rr];
                    float* Mrow = Mg + (size_t)rr * CPP;
                    #pragma unroll
                    for (int q = 0; q < 4; q++) {
                        const int cc = j0 + wn * 32 + q * 8 + (lane & 3) * 2;
                        const float d0 = acc[q][half * 2 + 0];
                        const float d1 = acc[q][half * 2 + 1];
                        if (cc + 1 < nc) {
                            float m0 = fmaf(-2.0f, d0, nx + nrm[nt + cc]);
                            float m1 = fmaf(-2.0f, d1, nx + nrm[nt + cc + 1]);
                            *(float2*)(Mrow + cc) = make_float2(m0, m1);
                            lmax = fmaxf(lmax, fmaxf(m0, m1));
                            tsum += m0 + m1;
                        } else if (cc < nc) {
                            float m0 = fmaf(-2.0f, d0, nx + nrm[nt + cc]);
                            Mrow[cc] = m0;
                            lmax = fmaxf(lmax, m0);
                            tsum += m0;
                        }
                    }
                }
                lsum += (double)tsum;
            }
            lmax = warpMaxF(lmax);
            lsum = warpSumD(lsum);
            __syncthreads();
            if (lane == 0) { s_f[wid] = lmax; s_d[wid] = lsum; }
            __syncthreads();
            if (wid == 0) {
                float  m2 = s_f[lane];
                double s2 = s_d[lane];
                m2 = warpMaxF(m2);
                s2 = warpSumD(s2);
                if (lane == 0) { g_pmax[grp][lb] = m2; g_psum[grp][lb] = s2; }
            }
        }
        GBAR();

        // ---------- B2: reduce GNB partials (identical fixed order in every block) ----------
        if (tid == 0) {
            float  dmax = -FLT_MAX;
            double dsum = 0.0;
            #pragma unroll 6
            for (int k2 = 0; k2 < GNB; k2++) {
                dmax = fmaxf(dmax, __ldcg(&g_pmax[grp][k2]));
                dsum += __ldcg(&g_psum[grp][k2]);
            }
            s_delta  = dmax;
            s_efflam = (float)(((double)nt * (double)nc) / dsum);
        }
        __syncthreads();
        const float delta  = s_delta;
        const float efflam = s_efflam;

        // ---------- B3: K = exp(-efflam*Mt)+eps (fp16, segment-permuted), K^T transpose ----------
        {
            const int rowStrips = RPP >> 5, colStrips = CPP >> 7;
            const int nStr = rowStrips * colStrips;
            const int srow = wid;
            const int tj = tid >> 3;
            const int io = (tid & 7) * 4;
            const float kdelta = fast_exp(-efflam * delta) + EPSK;

            for (int str = lb; str < nStr; str += GNB) {
                int sr = str / colStrips, sc = str - sr * colStrips;
                int i0 = sr << 5, j0 = sc << 7;
                int i = i0 + srow;
                float kq[4];
                #pragma unroll
                for (int q = 0; q < 4; q++) {
                    int j = j0 + lane * 4 + q;
                    float kv;
                    if (i < nt && j < nc) {
                        float m = __ldcg(&Mg[(size_t)i * CPP + j]);
                        kv = fast_exp(-efflam * m) + EPSK;
                    } else if (i == nt && j < nc) kv = kdelta;
                    else if (j == nc && i < nt)   kv = kdelta;
                    else if (i == nt && j == nc)  kv = 1.0f + EPSK;
                    else                          kv = 0.0f;
                    kq[q] = kv;
                }
                *(float4*)&sh[srow * 132 + lane * 4] = make_float4(kq[0], kq[1], kq[2], kq[3]);
                {
                    union { __half2 h[2]; uint2 u; } cv;
                    cv.h[0] = __floats2half2_rn(kq[0], kq[1]);
                    cv.h[1] = __floats2half2_rn(kq[2], kq[3]);
                    int halfOff = (j0 & ~255) + lane * 8 + ((j0 & 128) ? 4 : 0);
                    *(uint2*)&Kg[(size_t)i * CPP + halfOff] = cv.u;
                }
                __syncthreads();
                {
                    union { __half2 h[2]; uint2 u; } cv;
                    cv.h[0] = __floats2half2_rn(sh[(io+0)*132 + tj], sh[(io+1)*132 + tj]);
                    cv.h[1] = __floats2half2_rn(sh[(io+2)*132 + tj], sh[(io+3)*132 + tj]);
                    int ii = i0 + io;
                    int halfOff = (ii & ~255) + ((ii & 127) >> 2) * 8 + ((ii & 128) ? 4 : 0);
                    *(uint2*)&KTg[(size_t)(j0 + tj) * RPP + halfOff] = cv.u;
                }
                __syncthreads();
            }
            if (lb == 0) {
                for (int r2 = tid; r2 < RPP; r2 += NT)
                    ug[r2] = (r2 < nt) ? a_in : ((r2 == nt) ? a_last : 0.0f);
                for (int c2 = tid; c2 < CPP; c2 += NT)
                    if (c2 >= C) bvg[c2] = 0.0f;
            }
        }
        GBAR();

        // ---------- Sinkhorn: 20 iterations + final v pass ----------
        const int segU = RPP >> 8;
        const int segB = CPP >> 8;
        const float4* ug4  = (const float4*)ug;
        const float4* bvg4 = (const float4*)bvg;

        for (int it = 0; it <= ITS; it++) {
            // pass1: bv = b / (K^T u)  (u staged in smem, conflict-free permuted layout)
            for (int i4 = tid; i4 < (RPP >> 2); i4 += NT)
                ((float4*)sh)[i4] = __ldcg(ug4 + i4);
            __syncthreads();
            for (int cb = gw * 2; cb < C; cb += GW * 2) {
                const int c1 = (cb + 1 < C) ? (cb + 1) : cb;
                const uint4* Kr0 = (const uint4*)(KTg + (size_t)cb * RPP);
                const uint4* Kr1 = (const uint4*)(KTg + (size_t)c1 * RPP);
                float a00 = 0, a01 = 0, a10 = 0, a11 = 0;
                for (int sg = 0; sg < segU; sg++) {
                    uint4 k0 = __ldcg(Kr0 + sg * 32 + lane);
                    uint4 k1 = __ldcg(Kr1 + sg * 32 + lane);
                    float4 u0 = *(const float4*)&sh[sg * 256 + lane * 4];
                    float4 u1 = *(const float4*)&sh[sg * 256 + 128 + lane * 4];
                    const __half2* h0 = (const __half2*)&k0;
                    const __half2* h1 = (const __half2*)&k1;
                    float2 p00 = __half22float2(h0[0]), p01 = __half22float2(h0[1]);
                    float2 p02 = __half22float2(h0[2]), p03 = __half22float2(h0[3]);
                    float2 p10 = __half22float2(h1[0]), p11 = __half22float2(h1[1]);
                    float2 p12 = __half22float2(h1[2]), p13 = __half22float2(h1[3]);
                    a00 = fmaf(p00.x, u0.x, a00); a01 = fmaf(p00.y, u0.y, a01);
                    a00 = fmaf(p01.x, u0.z, a00); a01 = fmaf(p01.y, u0.w, a01);
                    a00 = fmaf(p02.x, u1.x, a00); a01 = fmaf(p02.y, u1.y, a01);
                    a00 = fmaf(p03.x, u1.z, a00); a01 = fmaf(p03.y, u1.w, a01);
                    a10 = fmaf(p10.x, u0.x, a10); a11 = fmaf(p10.y, u0.y, a11);
                    a10 = fmaf(p11.x, u0.z, a10); a11 = fmaf(p11.y, u0.w, a11);
                    a10 = fmaf(p12.x, u1.x, a10); a11 = fmaf(p12.y, u1.y, a11);
                    a10 = fmaf(p13.x, u1.z, a10); a11 = fmaf(p13.y, u1.w, a11);
                }
                float s0 = a00 + a01, s1 = a10 + a11;
                warpSum2F(s0, s1);
                if (lane == 0) {
                    bvg[cb] = ((cb < nc) ? b_in : b_last) / s0;
                    if (cb + 1 < C) bvg[cb + 1] = ((cb + 1 < nc) ? b_in : b_last) / s1;
                }
            }
            GBAR();
            if (it == ITS) break;

            // pass2: u = a / (K bv)
            for (int i4 = tid; i4 < (CPP >> 2); i4 += NT)
                ((float4*)sh)[i4] = __ldcg(bvg4 + i4);
            __syncthreads();
            for (int rb = gw * 2; rb < R; rb += GW * 2) {
                const int r1 = (rb + 1 < R) ? (rb + 1) : rb;
                const uint4* Kr0 = (const uint4*)(Kg + (size_t)rb * CPP);
                const uint4* Kr1 = (const uint4*)(Kg + (size_t)r1 * CPP);
                float a00 = 0, a01 = 0, a10 = 0, a11 = 0;
                for (int sg = 0; sg < segB; sg++) {
                    uint4 k0 = __ldcg(Kr0 + sg * 32 + lane);
                    uint4 k1 = __ldcg(Kr1 + sg * 32 + lane);
                    float4 u0 = *(const float4*)&sh[sg * 256 + lane * 4];
                    float4 u1 = *(const float4*)&sh[sg * 256 + 128 + lane * 4];
                    const __half2* h0 = (const __half2*)&k0;
                    const __half2* h1 = (const __half2*)&k1;
                    float2 p00 = __half22float2(h0[0]), p01 = __half22float2(h0[1]);
                    float2 p02 = __half22float2(h0[2]), p03 = __half22float2(h0[3]);
                    float2 p10 = __half22float2(h1[0]), p11 = __half22float2(h1[1]);
                    float2 p12 = __half22float2(h1[2]), p13 = __half22float2(h1[3]);
                    a00 = fmaf(p00.x, u0.x, a00); a01 = fmaf(p00.y, u0.y, a01);
                    a00 = fmaf(p01.x, u0.z, a00); a01 = fmaf(p01.y, u0.w, a01);
                    a00 = fmaf(p02.x, u1.x, a00); a01 = fmaf(p02.y, u1.y, a01);
                    a00 = fmaf(p03.x, u1.z, a00); a01 = fmaf(p03.y, u1.w, a01);
                    a10 = fmaf(p10.x, u0.x, a10); a11 = fmaf(p10.y, u0.y, a11);
                    a10 = fmaf(p11.x, u0.z, a10); a11 = fmaf(p11.y, u0.w, a11);
                    a10 = fmaf(p12.x, u1.x, a10); a11 = fmaf(p12.y, u1.y, a11);
                    a10 = fmaf(p13.x, u1.z, a10); a11 = fmaf(p13.y, u1.w, a11);
                }
                float s0 = a00 + a01, s1 = a10 + a11;
                warpSum2F(s0, s1);
                if (lane == 0) {
                    ug[rb] = ((rb < nt) ? a_in : a_last) / s0;
                    if (rb + 1 < R) ug[rb + 1] = ((rb + 1 < nt) ? a_in : a_last) / s1;
                }
            }
            GBAR();
        }

        // ---------- Final: 2 * sum u_i K_ij v_j Mt_ij ----------
        {
            for (int i4 = tid; i4 < (CPP >> 2); i4 += NT)
                ((float4*)sh)[i4] = __ldcg(bvg4 + i4);
            __syncthreads();
            double wacc = 0.0;
            for (int r2 = gw; r2 < R; r2 += GW) {
                const uint4*  Kr = (const uint4*)(Kg + (size_t)r2 * CPP);
                const float4* Mr = (const float4*)(Mg + (size_t)r2 * CPP);
                const bool lastRow = (r2 == nt);
                float acc = 0.0f;
                for (int sg = 0; sg < segB; sg++) {
                    uint4 kv = __ldcg(Kr + sg * 32 + lane);
                    const __half2* hp = (const __half2*)&kv;
                    float4 m0 = __ldcg(Mr + sg * 64 + lane);
                    float4 m1 = __ldcg(Mr + sg * 64 + 32 + lane);
                    float4 vv0 = *(const float4*)&sh[sg * 256 + lane * 4];
                    float4 vv1 = *(const float4*)&sh[sg * 256 + 128 + lane * 4];
                    float2 f0 = __half22float2(hp[0]);
                    float2 f1 = __half22float2(hp[1]);
                    float2 f2 = __half22float2(hp[2]);
                    float2 f3 = __half22float2(hp[3]);
                    int j1 = sg * 256 + lane * 4;
                    int j2 = j1 + 128;
                    float mt[8];
                    if (lastRow) {
                        mt[0] = (j1+0 < nc) ? delta : 0.0f;
                        mt[1] = (j1+1 < nc) ? delta : 0.0f;
                        mt[2] = (j1+2 < nc) ? delta : 0.0f;
                        mt[3] = (j1+3 < nc) ? delta : 0.0f;
                        mt[4] = (j2+0 < nc) ? delta : 0.0f;
                        mt[5] = (j2+1 < nc) ? delta : 0.0f;
                        mt[6] = (j2+2 < nc) ? delta : 0.0f;
                        mt[7] = (j2+3 < nc) ? delta : 0.0f;
                    } else {
                        mt[0] = (j1+0 < nc) ? m0.x : ((j1+0 == nc) ? delta : 0.0f);
                        mt[1] = (j1+1 < nc) ? m0.y : ((j1+1 == nc) ? delta : 0.0f);
                        mt[2] = (j1+2 < nc) ? m0.z : ((j1+2 == nc) ? delta : 0.0f);
                        mt[3] = (j1+3 < nc) ? m0.w : ((j1+3 == nc) ? delta : 0.0f);
                        mt[4] = (j2+0 < nc) ? m1.x : ((j2+0 == nc) ? delta : 0.0f);
                        mt[5] = (j2+1 < nc) ? m1.y : ((j2+1 == nc) ? delta : 0.0f);
                        mt[6] = (j2+2 < nc) ? m1.z : ((j2+2 == nc) ? delta : 0.0f);
                        mt[7] = (j2+3 < nc) ? m1.w : ((j2+3 == nc) ? delta : 0.0f);
                    }
                    acc = fmaf(f0.x * vv0.x, mt[0], acc);
                    acc = fmaf(f0.y * vv0.y, mt[1], acc);
                    acc = fmaf(f1.x * vv0.z, mt[2], acc);
                    acc = fmaf(f1.y * vv0.w, mt[3], acc);
                    acc = fmaf(f2.x * vv1.x, mt[4], acc);
                    acc = fmaf(f2.y * vv1.y, mt[5], acc);
                    acc = fmaf(f3.x * vv1.z, mt[6], acc);
                    acc = fmaf(f3.y * vv1.w, mt[7], acc);
                }
                acc = warpSumF(acc);
                if (lane == 0) wacc += (double)(__ldcg(&ug[r2]) * acc);
            }
            __syncthreads();
            if (lane == 0) s_d[wid] = wacc;
            __syncthreads();
            if (wid == 0) {
                double t2 = warpSumD(s_d[lane]);
                if (lane == 0) g_pres[grp][lb] = t2;
            }
        }
        GBAR();
        if (lb == 0 && tid == 0) {
            double ts = 0.0;
            #pragma unroll 6
            for (int k2 = 0; k2 < GNB; k2++) ts += __ldcg(&g_pres[grp][k2]);
            g_res[s] = 2.0 * ts;
        }
    }

    // ---------------- global combine ----------------
    __threadfence();
    __syncthreads();
    if (tid == 0) atomicAdd(&g_doneCnt, 1ULL);
    if (bid == 0 && tid == 0) {
        unsigned long long tgt = doneBase + (unsigned long long)NB;
        while (*(volatile unsigned long long*)&g_doneCnt < tgt) { __nanosleep(128); }
        __threadfence();
        double total = 0.0;
        for (int s = 0; s < S_; s++) total += __ldcg(&g_res[s]);
        out[0] = (float)total;
    }
}

extern "C" void kernel_launch(void* const* d_in, const int* in_sizes, int n_in,
                              void* d_out, int out_size) {
    const float* X = (const float*)d_in[0];
    const int*   T = (const int*)d_in[1];
    float* out = (float*)d_out;
    (void)in_sizes; (void)n_in; (void)out_size;
    cudaFuncSetAttribute(sinkhorn_all, cudaFuncAttributeMaxDynamicSharedMemorySize, SMEM_BYTES);
    sinkhorn_all<<<NB, NT, SMEM_BYTES>>>(X, T, out);
}